// round 16
// baseline (speedup 1.0000x reference)
#include <cuda_runtime.h>

#define BATCH 16
#define HH 512
#define WW 512
#define HWSZ (HH * WW)
#define TR 8

// ---- scratch (no allocations allowed; zero-initialized at module load) ----
__device__ float g_colsum[BATCH][WW];    // de_h summed over H, per column ([0..510] used)
__device__ float g_rowsum[BATCH][HH];    // de_v summed over W, per row ([0..510] + phantom 511)
__device__ __align__(16) int g_dec[BATCH][4];   // kh, bh, kv, bv (rewritten every replay)

// PDL: block until the programmatic predecessor grid has completed (implicit
// trigger at predecessor end -> its memory is visible after this returns).
__device__ __forceinline__ void gdc_wait() {
    asm volatile("griddepcontrol.wait;" ::: "memory");
}

// evict-first 128-bit store: keep the streamed output OUT of persistent L2
// so the 100.7 MB of inputs can stay L2-resident across graph replays.
__device__ __forceinline__ void stcs128(float4* p, float4 v) {
    asm volatile("st.global.cs.v4.f32 [%0], {%1, %2, %3, %4};"
                 :: "l"(p), "f"(v.x), "f"(v.y), "f"(v.z), "f"(v.w) : "memory");
}

__device__ __forceinline__ float lum1(const float* p) {
    return 0.299f * p[0] + 0.587f * p[HWSZ] + 0.114f * p[2 * HWSZ];
}
__device__ __forceinline__ float2 lum2(float2 c0, float2 c1, float2 c2) {
    float2 l;
    l.x = 0.299f * c0.x + 0.587f * c1.x + 0.114f * c2.x;
    l.y = 0.299f * c0.y + 0.587f * c1.y + 0.114f * c2.y;
    return l;
}
// clipped excess: max(|t0-t1| - |r0-r1|, 0)
__device__ __forceinline__ float dexc(float t0, float t1, float r0, float r1) {
    return fmaxf(fabsf(t0 - t1) - fabsf(r0 - r1), 0.0f);
}

// -------------------------------------------------------------------------
// Kernel 1: PURE barrier-free streaming reduction into LINE SUMS — exact
// proven body (22.9us). Warp = 64-col x TR-row strip, float2 per lane.
// grid: BATCH * 64 tiles * 8 strips = 8192 warps, 8 warps/block.
// -------------------------------------------------------------------------
__global__ __launch_bounds__(256) void jb_accum_kernel(
    const float* __restrict__ ref, const float* __restrict__ tgt)
{
    const int gw    = blockIdx.x * 8 + (threadIdx.x >> 5);
    const int lane  = threadIdx.x & 31;
    const int b     = gw >> 9;            // 512 warps per batch
    const int rem   = gw & 511;
    const int tile  = rem >> 3;
    const int strip = rem & 7;
    const int r0    = tile * TR;
    const int c0    = strip * 64 + lane * 2;

    const float* rB = ref + (size_t)b * 3 * HWSZ;
    const float* tB = tgt + (size_t)b * 3 * HWSZ;

    const bool bnd_load = (lane == 31) && (strip < 7);   // col c0+2 in next strip
    const bool bnd_skip = (lane == 31) && (strip == 7);  // col 511: no right neighbor

    float2 cacc = make_float2(0.f, 0.f);
    float2 plr, plt;

    #pragma unroll 3
    for (int i = 0; i <= TR; ++i) {
        const int r = min(r0 + i, HH - 1);       // clamp phantom row (dv==0 there)
        const float* rp = rB + (size_t)r * WW + c0;
        const float* tp = tB + (size_t)r * WW + c0;
        float2 rc0 = *reinterpret_cast<const float2*>(rp);
        float2 rc1 = *reinterpret_cast<const float2*>(rp + HWSZ);
        float2 rc2 = *reinterpret_cast<const float2*>(rp + 2 * HWSZ);
        float2 tc0 = *reinterpret_cast<const float2*>(tp);
        float2 tc1 = *reinterpret_cast<const float2*>(tp + HWSZ);
        float2 tc2 = *reinterpret_cast<const float2*>(tp + 2 * HWSZ);
        float2 lr = lum2(rc0, rc1, rc2);
        float2 lt = lum2(tc0, tc1, tc2);

        if (i < TR) {
            float nr = __shfl_down_sync(0xffffffffu, lr.x, 1);
            float nt = __shfl_down_sync(0xffffffffu, lt.x, 1);
            if (bnd_load) {                  // boundary luminance (col c0+2)
                nr = lum1(rp + 2);
                nt = lum1(tp + 2);
            }
            cacc.x += dexc(lt.x, lt.y, lr.x, lr.y);
            if (!bnd_skip)
                cacc.y += dexc(lt.y, nt, lr.y, nr);
        }

        if (i > 0) {
            float dv = dexc(plt.x, lt.x, plr.x, lr.x)
                     + dexc(plt.y, lt.y, plr.y, lr.y);
            #pragma unroll
            for (int off = 16; off > 0; off >>= 1)
                dv += __shfl_down_sync(0xffffffffu, dv, off);
            if (lane == 0)
                atomicAdd(&g_rowsum[b][r0 + i - 1], dv);  // phantom -> idx 511 (unused)
        }
        plr = lr; plt = lt;
    }

    atomicAdd(&g_colsum[b][c0 + 0], cacc.x);
    atomicAdd(&g_colsum[b][c0 + 1], cacc.y);
}

// -------------------------------------------------------------------------
// Kernel 2: per-batch phase decision -> g_dec[b]. Also ZEROES the line
// sums it consumed (replay hygiene). PDL-waits on accum completion.
// grid: BATCH blocks x 128 threads (0..63 cols/h, 64..127 rows/v).
// -------------------------------------------------------------------------
__global__ void jb_decide_kernel()
{
    gdc_wait();                            // accum grid complete + visible

    const int b = blockIdx.x;
    const int t = threadIdx.x;

    __shared__ float ph[2][8];
    if (t < 16) ph[t >> 3][t & 7] = 0.0f;
    __syncthreads();

    const int grp = t >> 6;                // 0 = h (cols), 1 = v (rows)
    const int i0  = t & 63;
    float* src = grp ? g_rowsum[b] : g_colsum[b];

    float acc = 0.0f;
    for (int i = i0; i < 512; i += 64) {
        if (i < 511) acc += src[i] * (1.0f / 512.0f);   // line mean
        src[i] = 0.0f;                     // reset for next graph replay
    }
    atomicAdd(&ph[grp][i0 & 7], acc);
    __syncthreads();

    if (t < 2) {
        float total = 0.0f;
        #pragma unroll
        for (int k = 0; k < 8; ++k) total += ph[t][k];
        float best_r = -1.0f;
        int   best_k = 0;
        #pragma unroll
        for (int k = 0; k < 8; ++k) {
            float cnt   = (k < 7) ? 64.0f : 63.0f;   // 511 lines: phases 0..6 have 64
            float a_k   = ph[t][k] / cnt;
            float bg    = (total - ph[t][k]) / (511.0f - cnt);
            float ratio = a_k / (bg + 1e-8f);
            if (ratio > best_r) { best_r = ratio; best_k = k; }  // first-max (argmax)
        }
        g_dec[b][t * 2 + 0] = best_k;
        g_dec[b][t * 2 + 1] = best_r > (1.0f / 0.35f);
    }
}

// -------------------------------------------------------------------------
// Kernel 3: PURE mask paint, EVICT-FIRST stores (st.global.cs) so the
// 16.8 MB output never competes with the inputs for L2 residency.
// 512 blocks x 256 threads x 32 floats (8 x STG.128). PDL-waits on decide.
// -------------------------------------------------------------------------
__global__ __launch_bounds__(256) void jb_write_kernel(float* __restrict__ out)
{
    const int idx = blockIdx.x * 256 + threadIdx.x;  // B*H*W/32 = 131072 threads
    const int cg  = idx & 15;             // 16 chunks of 32 cols per row
    const int r   = (idx >> 4) & (HH - 1);
    const int b   = idx >> 13;            // 8192 threads per batch (block-aligned)

    gdc_wait();                            // decide grid complete + g_dec visible

    const int4 d = __ldg(reinterpret_cast<const int4*>(&g_dec[b][0]));  // kh,bh,kv,bv
    const int kh = d.x, bh = d.y, kv = d.z, bv = d.w;

    const bool vrow = bv && ((r & 7) == kv) && (r < HH - 1);
    const bool tail = (cg == 15);         // chunk containing col 511

    float4 o[8];
    float* op = reinterpret_cast<float*>(o);
    #pragma unroll
    for (int j = 0; j < 32; ++j) {
        bool vcol = bh && ((j & 7) == kh) && !(tail && j == 31);
        op[j] = (vrow || vcol) ? 1.0f : 0.0f;
    }
    float4* dst = reinterpret_cast<float4*>(out + (size_t)idx * 32);
    #pragma unroll
    for (int j = 0; j < 8; ++j) stcs128(dst + j, o[j]);
}

// -------------------------------------------------------------------------
extern "C" void kernel_launch(void* const* d_in, const int* in_sizes, int n_in,
                              void* d_out, int out_size)
{
    const float* ref = (const float*)d_in[0];
    const float* tgt = (const float*)d_in[1];
    float* out = (float*)d_out;

    // 16 batches * 64 tiles * 8 strips = 8192 warps -> 1024 blocks of 8 warps
    jb_accum_kernel<<<1024, 256>>>(ref, tgt);

    // PDL: dependent grids launch while predecessor drains; griddepcontrol.wait
    // inside each kernel provides the actual ordering.
    cudaLaunchAttribute attr[1];
    attr[0].id = cudaLaunchAttributeProgrammaticStreamSerialization;
    attr[0].val.programmaticStreamSerializationAllowed = 1;

    {
        cudaLaunchConfig_t cfg = {};
        cfg.gridDim  = dim3(BATCH);
        cfg.blockDim = dim3(128);
        cfg.stream   = 0;
        cfg.attrs    = attr;
        cfg.numAttrs = 1;
        cudaLaunchKernelEx(&cfg, jb_decide_kernel);
    }
    {
        cudaLaunchConfig_t cfg = {};
        cfg.gridDim  = dim3(512);
        cfg.blockDim = dim3(256);
        cfg.stream   = 0;
        cfg.attrs    = attr;
        cfg.numAttrs = 1;
        cudaLaunchKernelEx(&cfg, jb_write_kernel, out);
    }
}

// round 17
// speedup vs baseline: 1.1539x; 1.1539x over previous
#include <cuda_runtime.h>

#define BATCH 16
#define HH 512
#define WW 512
#define HWSZ (HH * WW)
#define TR 8

// ---- scratch (no allocations allowed; zero-initialized at module load) ----
__device__ float g_colsum[BATCH][WW];    // de_h summed over H, per column ([0..510] used)
__device__ float g_rowsum[BATCH][HH];    // de_v summed over W, per row ([0..510] + phantom 511)
__device__ __align__(16) int g_dec[BATCH][4];   // kh, bh, kv, bv (rewritten every replay)

// PDL: block until the programmatic predecessor grid has completed (implicit
// trigger at predecessor end -> its memory is visible after this returns).
__device__ __forceinline__ void gdc_wait() {
    asm volatile("griddepcontrol.wait;" ::: "memory");
}

__device__ __forceinline__ float lum1(const float* p) {
    return 0.299f * p[0] + 0.587f * p[HWSZ] + 0.114f * p[2 * HWSZ];
}
__device__ __forceinline__ float2 lum2(float2 c0, float2 c1, float2 c2) {
    float2 l;
    l.x = 0.299f * c0.x + 0.587f * c1.x + 0.114f * c2.x;
    l.y = 0.299f * c0.y + 0.587f * c1.y + 0.114f * c2.y;
    return l;
}
// clipped excess: max(|t0-t1| - |r0-r1|, 0)
__device__ __forceinline__ float dexc(float t0, float t1, float r0, float r1) {
    return fmaxf(fabsf(t0 - t1) - fabsf(r0 - r1), 0.0f);
}

// -------------------------------------------------------------------------
// Kernel 1: streaming reduction into LINE SUMS (proven 22.9us body) + each
// warp ZERO-FILLS its own 8x64 output region at the end (fire-and-forget
// stores ride the kernel's spare bandwidth; no sync needed).
// grid: BATCH * 64 tiles * 8 strips = 8192 warps, 8 warps/block.
// -------------------------------------------------------------------------
__global__ __launch_bounds__(256) void jb_accum_kernel(
    const float* __restrict__ ref, const float* __restrict__ tgt,
    float* __restrict__ out)
{
    const int gw    = blockIdx.x * 8 + (threadIdx.x >> 5);
    const int lane  = threadIdx.x & 31;
    const int b     = gw >> 9;            // 512 warps per batch
    const int rem   = gw & 511;
    const int tile  = rem >> 3;
    const int strip = rem & 7;
    const int r0    = tile * TR;
    const int c0    = strip * 64 + lane * 2;

    const float* rB = ref + (size_t)b * 3 * HWSZ;
    const float* tB = tgt + (size_t)b * 3 * HWSZ;

    const bool bnd_load = (lane == 31) && (strip < 7);   // col c0+2 in next strip
    const bool bnd_skip = (lane == 31) && (strip == 7);  // col 511: no right neighbor

    float2 cacc = make_float2(0.f, 0.f);
    float2 plr, plt;

    #pragma unroll 3
    for (int i = 0; i <= TR; ++i) {
        const int r = min(r0 + i, HH - 1);       // clamp phantom row (dv==0 there)
        const float* rp = rB + (size_t)r * WW + c0;
        const float* tp = tB + (size_t)r * WW + c0;
        float2 rc0 = *reinterpret_cast<const float2*>(rp);
        float2 rc1 = *reinterpret_cast<const float2*>(rp + HWSZ);
        float2 rc2 = *reinterpret_cast<const float2*>(rp + 2 * HWSZ);
        float2 tc0 = *reinterpret_cast<const float2*>(tp);
        float2 tc1 = *reinterpret_cast<const float2*>(tp + HWSZ);
        float2 tc2 = *reinterpret_cast<const float2*>(tp + 2 * HWSZ);
        float2 lr = lum2(rc0, rc1, rc2);
        float2 lt = lum2(tc0, tc1, tc2);

        if (i < TR) {
            float nr = __shfl_down_sync(0xffffffffu, lr.x, 1);
            float nt = __shfl_down_sync(0xffffffffu, lt.x, 1);
            if (bnd_load) {                  // boundary luminance (col c0+2)
                nr = lum1(rp + 2);
                nt = lum1(tp + 2);
            }
            cacc.x += dexc(lt.x, lt.y, lr.x, lr.y);
            if (!bnd_skip)
                cacc.y += dexc(lt.y, nt, lr.y, nr);
        }

        if (i > 0) {
            float dv = dexc(plt.x, lt.x, plr.x, lr.x)
                     + dexc(plt.y, lt.y, plr.y, lr.y);
            #pragma unroll
            for (int off = 16; off > 0; off >>= 1)
                dv += __shfl_down_sync(0xffffffffu, dv, off);
            if (lane == 0)
                atomicAdd(&g_rowsum[b][r0 + i - 1], dv);  // phantom -> idx 511 (unused)
        }
        plr = lr; plt = lt;
    }

    atomicAdd(&g_colsum[b][c0 + 0], cacc.x);
    atomicAdd(&g_colsum[b][c0 + 1], cacc.y);

    // ---- zero-fill this warp's 8x64 output region ----
    // lane l: row r0 + (l>>2), cols strip*64 + (l&3)*16 .. +15  (4 x STG.128)
    {
        float4 z = make_float4(0.f, 0.f, 0.f, 0.f);
        float4* po = reinterpret_cast<float4*>(
            out + ((size_t)b * HH + r0 + (lane >> 2)) * WW + strip * 64 + (lane & 3) * 16);
        po[0] = z; po[1] = z; po[2] = z; po[3] = z;
    }
}

// -------------------------------------------------------------------------
// Kernel 2: per-batch phase decision -> g_dec[b]. Also ZEROES the line
// sums it consumed (replay hygiene). PDL-waits on accum completion.
// grid: BATCH blocks x 128 threads (0..63 cols/h, 64..127 rows/v).
// -------------------------------------------------------------------------
__global__ void jb_decide_kernel()
{
    gdc_wait();                            // accum grid complete + visible

    const int b = blockIdx.x;
    const int t = threadIdx.x;

    __shared__ float ph[2][8];
    if (t < 16) ph[t >> 3][t & 7] = 0.0f;
    __syncthreads();

    const int grp = t >> 6;                // 0 = h (cols), 1 = v (rows)
    const int i0  = t & 63;
    float* src = grp ? g_rowsum[b] : g_colsum[b];

    float acc = 0.0f;
    for (int i = i0; i < 512; i += 64) {
        if (i < 511) acc += src[i] * (1.0f / 512.0f);   // line mean
        src[i] = 0.0f;                     // reset for next graph replay
    }
    atomicAdd(&ph[grp][i0 & 7], acc);
    __syncthreads();

    if (t < 2) {
        float total = 0.0f;
        #pragma unroll
        for (int k = 0; k < 8; ++k) total += ph[t][k];
        float best_r = -1.0f;
        int   best_k = 0;
        #pragma unroll
        for (int k = 0; k < 8; ++k) {
            float cnt   = (k < 7) ? 64.0f : 63.0f;   // 511 lines: phases 0..6 have 64
            float a_k   = ph[t][k] / cnt;
            float bg    = (total - ph[t][k]) / (511.0f - cnt);
            float ratio = a_k / (bg + 1e-8f);
            if (ratio > best_r) { best_r = ratio; best_k = k; }  // first-max (argmax)
        }
        g_dec[b][t * 2 + 0] = best_k;
        g_dec[b][t * 2 + 1] = best_r > (1.0f / 0.35f);
    }
}

// -------------------------------------------------------------------------
// Kernel 3: SPARSE paint. Output is already zero (accum did it); only the
// winning phase lines get 1.0 — and only if blocked. Zero work on
// non-blocked batches. PDL-waits on decide.
// grid: BATCH * 8 segments = 128 blocks x 256 threads; each block owns a
// 64-row segment of one batch image.
// -------------------------------------------------------------------------
__global__ __launch_bounds__(256) void jb_paint_kernel(float* __restrict__ out)
{
    gdc_wait();                            // decide grid complete + g_dec visible

    const int b   = blockIdx.x >> 3;       // 8 segment-blocks per batch
    const int seg = blockIdx.x & 7;        // 64-row segment
    const int t   = threadIdx.x;

    const int4 d = __ldg(reinterpret_cast<const int4*>(&g_dec[b][0]));  // kh,bh,kv,bv

    // ---- column paint: cols kh+8j (j=0..63), all 64 rows of my segment ----
    if (d.y) {
        const int kh = d.x;
        for (int i = t; i < 64 * 64; i += 256) {
            const int row = seg * 64 + (i >> 6);
            const int col = kh + ((i & 63) << 3);
            if (col < WW - 1)
                out[((size_t)b * HH + row) * WW + col] = 1.0f;
        }
    }

    // ---- row paint: rows seg*64 + kv + 8j (j=0..7), full 512 cols ----
    if (d.w) {
        const int kv = d.z;
        const float4 one = make_float4(1.f, 1.f, 1.f, 1.f);
        for (int i = t; i < 8 * 128; i += 256) {       // 8 rows x 128 float4
            const int row = seg * 64 + kv + ((i >> 7) << 3);
            const int c4  = i & 127;
            if (row < HH - 1)
                reinterpret_cast<float4*>(out + ((size_t)b * HH + row) * WW)[c4] = one;
        }
    }
}

// -------------------------------------------------------------------------
extern "C" void kernel_launch(void* const* d_in, const int* in_sizes, int n_in,
                              void* d_out, int out_size)
{
    const float* ref = (const float*)d_in[0];
    const float* tgt = (const float*)d_in[1];
    float* out = (float*)d_out;

    // 16 batches * 64 tiles * 8 strips = 8192 warps -> 1024 blocks of 8 warps
    jb_accum_kernel<<<1024, 256>>>(ref, tgt, out);

    // PDL: dependent grids launch while predecessor drains; griddepcontrol.wait
    // inside each kernel provides the actual ordering.
    cudaLaunchAttribute attr[1];
    attr[0].id = cudaLaunchAttributeProgrammaticStreamSerialization;
    attr[0].val.programmaticStreamSerializationAllowed = 1;

    {
        cudaLaunchConfig_t cfg = {};
        cfg.gridDim  = dim3(BATCH);
        cfg.blockDim = dim3(128);
        cfg.stream   = 0;
        cfg.attrs    = attr;
        cfg.numAttrs = 1;
        cudaLaunchKernelEx(&cfg, jb_decide_kernel);
    }
    {
        cudaLaunchConfig_t cfg = {};
        cfg.gridDim  = dim3(BATCH * 8);
        cfg.blockDim = dim3(256);
        cfg.stream   = 0;
        cfg.attrs    = attr;
        cfg.numAttrs = 1;
        cudaLaunchKernelEx(&cfg, jb_paint_kernel, out);
    }
}